// round 5
// baseline (speedup 1.0000x reference)
#include <cuda_runtime.h>
#include <stdint.h>

// ProbabilisticPrediction fused kernel, R5: transposed activations + packed
// fma.rn.f32x2 (half the FMA issues), MUFU lg2-based Gumbel, 8 rows/block,
// 1024 threads (32 warps/SM). Gumbel-argmax (JAX threefry partitionable)
// selects one mixture component per (b,q); MLP evaluated only there.

#define B_   4
#define QL_  256
#define CL_  512
#define DIM_ 128
#define YD_  16
#define R_   8

typedef unsigned long long ull;

#define FMA2(d, a, b, c) \
    asm("fma.rn.f32x2 %0, %1, %2, %3;" : "=l"(d) : "l"(a), "l"(b), "l"(c))
#define ADD2(d, a, b) \
    asm("add.rn.f32x2 %0, %1, %2;" : "=l"(d) : "l"(a), "l"(b))
#define PACK2(d, lo, hi) \
    asm("mov.b64 %0, {%1, %2};" : "=l"(d) : "f"(lo), "f"(hi))
#define UNPACK2(lo, hi, s) \
    asm("mov.b64 {%0, %1}, %2;" : "=f"(lo), "=f"(hi) : "l"(s))

// ---------------------------------------------------------------- threefry2x32
__host__ __device__ inline void tf2x32(uint32_t k0, uint32_t k1,
                                       uint32_t c0, uint32_t c1,
                                       uint32_t& o0, uint32_t& o1) {
    uint32_t k2 = k0 ^ k1 ^ 0x1BD11BDAu;
    uint32_t x0 = c0 + k0, x1 = c1 + k1;
#define TFR(d) do { x0 += x1; x1 = (x1 << (d)) | (x1 >> (32 - (d))); x1 ^= x0; } while (0)
    TFR(13); TFR(15); TFR(26); TFR(6);   x0 += k1; x1 += k2 + 1u;
    TFR(17); TFR(29); TFR(16); TFR(24);  x0 += k2; x1 += k0 + 2u;
    TFR(13); TFR(15); TFR(26); TFR(6);   x0 += k0; x1 += k1 + 3u;
    TFR(17); TFR(29); TFR(16); TFR(24);  x0 += k1; x1 += k2 + 4u;
    TFR(13); TFR(15); TFR(26); TFR(6);   x0 += k2; x1 += k0 + 5u;
#undef TFR
    o0 = x0; o1 = x1;
}

__device__ inline uint32_t jax_bits(uint32_t k0, uint32_t k1, uint32_t j) {
    uint32_t o0, o1;
    tf2x32(k0, k1, 0u, j, o0, o1);   // partitionable: 64-bit iota (0, j)
    return o0 ^ o1;
}

__device__ inline float bits_to_unit(uint32_t b) {      // [0, 1)
    return __uint_as_float((b >> 9) | 0x3f800000u) - 1.0f;
}

// XLA ErfInv32 (Giles) -- matches jax.random.normal exactly.
__device__ inline float erfinv_xla(float x) {
    float w = -log1pf(-x * x);
    float p;
    if (w < 5.0f) {
        w -= 2.5f;
        p =            2.81022636e-08f;
        p = fmaf(p, w, 3.43273939e-07f);
        p = fmaf(p, w, -3.5233877e-06f);
        p = fmaf(p, w, -4.39150654e-06f);
        p = fmaf(p, w, 0.00021858087f);
        p = fmaf(p, w, -0.00125372503f);
        p = fmaf(p, w, -0.00417768164f);
        p = fmaf(p, w, 0.246640727f);
        p = fmaf(p, w, 1.50140941f);
    } else {
        w = sqrtf(w) - 3.0f;
        p =            -0.000200214257f;
        p = fmaf(p, w, 0.000100950558f);
        p = fmaf(p, w, 0.00134934322f);
        p = fmaf(p, w, -0.00367342844f);
        p = fmaf(p, w, 0.00573950773f);
        p = fmaf(p, w, -0.0076224613f);
        p = fmaf(p, w, 0.00943887047f);
        p = fmaf(p, w, 1.00167406f);
        p = fmaf(p, w, 2.83297682f);
    }
    return p * x;
}

// ---------------------------------------------------------------------- kernel
__global__ __launch_bounds__(1024, 1)
void pp_fused_kernel(const float* __restrict__ q,
                     const float* __restrict__ f_embed,
                     const float* __restrict__ att_logits,
                     const float* __restrict__ W1q,
                     const float* __restrict__ W1f,
                     const float* __restrict__ b1,
                     const float* __restrict__ W2,
                     const float* __restrict__ b2,
                     const float* __restrict__ Wout,
                     const float* __restrict__ bout,
                     float* __restrict__ out,
                     uint32_t kc0, uint32_t kc1,
                     uint32_t ke0, uint32_t ke1)
{
    const int t   = threadIdx.x;         // 0..1023
    const int w   = t >> 5;              // warp 0..31
    const int ln  = t & 31;
    const int bq0 = blockIdx.x * R_;
    const int b   = bq0 >> 8;            // all R_ rows share b (8 | 256)

    __shared__ float sQt[DIM_ * R_];     // q transposed [d][r]; later h2
    __shared__ float sFt[DIM_ * R_];     // selected f rows, transposed
    __shared__ float sHt[DIM_ * R_];     // h1 transposed
    __shared__ float sPar[8 * R_ * DIM_];// packed partials (32KB)
    __shared__ float sO[R_ * 2 * YD_];
    __shared__ float sVal[32];
    __shared__ int   sIdxW[32];
    __shared__ int   sIdxRow[R_];

    // Prefetch q rows transposed: sQt[c*8 + r] (coalesced LDG).
    {
        const int r = t >> 7, cc = t & 127;
        sQt[cc * 8 + r] = q[(size_t)(bq0 + r) * DIM_ + cc];
    }

    // -------- Phase 1: Gumbel-argmax; row r = w>>2, sub-range sub = w&3 -----
    {
        const int r = w >> 2, sub = w & 3;
        const int bq = bq0 + r;
        const float* lrow = att_logits + (size_t)bq * CL_;
        const float TINY = 1.17549435e-38f;
        float best = -__int_as_float(0x7f800000);
        int bi = 0;
#pragma unroll
        for (int i = 0; i < 4; ++i) {
            int c = sub * 128 + i * 32 + ln;
            uint32_t j = (uint32_t)bq * (uint32_t)CL_ + (uint32_t)c;
            float u = bits_to_unit(jax_bits(kc0, kc1, j));
            u = fmaxf(TINY, u * (1.0f - TINY) + TINY);
            // g = -log(-log(u)) via 2x MUFU lg2:
            //   g = -ln2*log2(-log2(u)) - ln(ln2)
            float lg1; asm("lg2.approx.f32 %0, %1;" : "=f"(lg1) : "f"(u));
            float L = -lg1;
            float lg2v; asm("lg2.approx.f32 %0, %1;" : "=f"(lg2v) : "f"(L));
            float g = fmaf(-0.693147180559945f, lg2v, 0.366512920581664f);
            float v = g + lrow[c];
            if (v > best || (v == best && c < bi)) { best = v; bi = c; }
        }
#pragma unroll
        for (int off = 16; off; off >>= 1) {
            float v2 = __shfl_xor_sync(0xffffffffu, best, off);
            int   i2 = __shfl_xor_sync(0xffffffffu, bi,   off);
            if (v2 > best || (v2 == best && i2 < bi)) { best = v2; bi = i2; }
        }
        if (ln == 0) { sVal[w] = best; sIdxW[w] = bi; }
    }
    __syncthreads();
    if (t < R_) {
        float bv = sVal[t * 4]; int bj = sIdxW[t * 4];
#pragma unroll
        for (int k = 1; k < 4; ++k) {
            float v2 = sVal[t * 4 + k]; int i2 = sIdxW[t * 4 + k];
            if (v2 > bv || (v2 == bv && i2 < bj)) { bv = v2; bj = i2; }
        }
        sIdxRow[t] = bj;
    }
    __syncthreads();
    {   // gather selected f rows transposed (coalesced LDG)
        const int r = t >> 7, cc = t & 127;
        sFt[cc * 8 + r] = f_embed[((size_t)b * CL_ + sIdxRow[r]) * DIM_ + cc];
    }
    __syncthreads();

    const int c   = t & 127;             // output column
    const int oct = t >> 7;              // d-octant (16 d's each)

    // -------- Layer 1: h = relu(q@W1q + f@W1f + b1), packed f32x2 -----------
    {
        ull acc0 = 0, acc1 = 0, acc2 = 0, acc3 = 0;
        const float* wqp = W1q + c;
        const float* wfp = W1f + c;
#pragma unroll
        for (int i = 0; i < 16; ++i) {
            const int d = oct * 16 + i;
            float wq = wqp[d * DIM_];
            float wf = wfp[d * DIM_];
            ull wq2, wf2;
            PACK2(wq2, wq, wq); PACK2(wf2, wf, wf);
            ulonglong2 qv0 = *(const ulonglong2*)(sQt + d * 8);
            ulonglong2 qv1 = *(const ulonglong2*)(sQt + d * 8 + 4);
            ulonglong2 fv0 = *(const ulonglong2*)(sFt + d * 8);
            ulonglong2 fv1 = *(const ulonglong2*)(sFt + d * 8 + 4);
            FMA2(acc0, qv0.x, wq2, acc0); FMA2(acc1, qv0.y, wq2, acc1);
            FMA2(acc2, qv1.x, wq2, acc2); FMA2(acc3, qv1.y, wq2, acc3);
            FMA2(acc0, fv0.x, wf2, acc0); FMA2(acc1, fv0.y, wf2, acc1);
            FMA2(acc2, fv1.x, wf2, acc2); FMA2(acc3, fv1.y, wf2, acc3);
        }
        ull* P = (ull*)sPar;
        P[oct * 512 + 0 * 128 + c] = acc0;
        P[oct * 512 + 1 * 128 + c] = acc1;
        P[oct * 512 + 2 * 128 + c] = acc2;
        P[oct * 512 + 3 * 128 + c] = acc3;
    }
    __syncthreads();
    if (t < 512) {   // reduce 8 octant partials, bias+relu, store transposed
        const int rp = t >> 7, cc = t & 127;
        const ull* P = (const ull*)sPar;
        ull s = P[rp * 128 + cc];
#pragma unroll
        for (int k = 1; k < 8; ++k) ADD2(s, s, P[k * 512 + rp * 128 + cc]);
        float lo, hi; UNPACK2(lo, hi, s);
        float bb = b1[cc];
        *(float2*)(sHt + cc * 8 + rp * 2) =
            make_float2(fmaxf(lo + bb, 0.f), fmaxf(hi + bb, 0.f));
    }
    __syncthreads();

    // -------- Layer 2: h2 = relu(h@W2 + b2), packed f32x2 -------------------
    {
        ull acc0 = 0, acc1 = 0, acc2 = 0, acc3 = 0;
        const float* w2p = W2 + c;
#pragma unroll
        for (int i = 0; i < 16; ++i) {
            const int d = oct * 16 + i;
            float wv = w2p[d * DIM_];
            ull wv2; PACK2(wv2, wv, wv);
            ulonglong2 hv0 = *(const ulonglong2*)(sHt + d * 8);
            ulonglong2 hv1 = *(const ulonglong2*)(sHt + d * 8 + 4);
            FMA2(acc0, hv0.x, wv2, acc0); FMA2(acc1, hv0.y, wv2, acc1);
            FMA2(acc2, hv1.x, wv2, acc2); FMA2(acc3, hv1.y, wv2, acc3);
        }
        ull* P = (ull*)sPar;
        P[oct * 512 + 0 * 128 + c] = acc0;
        P[oct * 512 + 1 * 128 + c] = acc1;
        P[oct * 512 + 2 * 128 + c] = acc2;
        P[oct * 512 + 3 * 128 + c] = acc3;
    }
    __syncthreads();
    if (t < 512) {
        const int rp = t >> 7, cc = t & 127;
        const ull* P = (const ull*)sPar;
        ull s = P[rp * 128 + cc];
#pragma unroll
        for (int k = 1; k < 8; ++k) ADD2(s, s, P[k * 512 + rp * 128 + cc]);
        float lo, hi; UNPACK2(lo, hi, s);
        float bb = b2[cc];
        *(float2*)(sQt + cc * 8 + rp * 2) =                       // sQt := h2
            make_float2(fmaxf(lo + bb, 0.f), fmaxf(hi + bb, 0.f));
    }
    __syncthreads();

    // -------- Layer 3: out = h2@Wout + bout, packed f32x2 -------------------
    {
        const int p  = t >> 7;           // k-group 0..7 (16 k's)
        const int rp = (t >> 5) & 3;     // row pair
        const int o  = ln;               // output column 0..31
        ull acc = 0;
#pragma unroll
        for (int i = 0; i < 16; ++i) {
            const int k = p * 16 + i;
            ull hv = *(const ull*)(sQt + k * 8 + rp * 2);
            float wv = Wout[k * 32 + o];
            ull wv2; PACK2(wv2, wv, wv);
            FMA2(acc, hv, wv2, acc);
        }
        ((ull*)sPar)[p * 128 + rp * 32 + o] = acc;
    }
    __syncthreads();
    if (t < 128) {
        const int rp = t >> 5, o = t & 31;
        const ull* P = (const ull*)sPar;
        ull s = P[t];
#pragma unroll
        for (int k = 1; k < 8; ++k) ADD2(s, s, P[k * 128 + t]);
        float lo, hi; UNPACK2(lo, hi, s);
        float bb = bout[o];
        sO[(2 * rp) * 32 + o]     = lo + bb;
        sO[(2 * rp + 1) * 32 + o] = hi + bb;
    }
    __syncthreads();

    // -------- Sample: y = mu + softplus(max(-15,s)) * eps -------------------
    if (t < R_ * YD_) {                  // 128 threads
        const int rr = t >> 4, y = t & 15;
        uint32_t m = (uint32_t)(bq0 + rr) * (uint32_t)YD_ + (uint32_t)y;
        float u = bits_to_unit(jax_bits(ke0, ke1, m));
        const float lo = -0.99999994f;
        float x = fmaxf(lo, u * (1.0f - lo) + lo);
        float eps = 1.41421356237f * erfinv_xla(x);
        float s = fmaxf(-15.0f, sO[rr * 32 + YD_ + y]);
        float sigma = fmaxf(s, 0.0f) + log1pf(expf(-fabsf(s)));
        out[(size_t)bq0 * YD_ + t] = fmaf(sigma, eps, sO[rr * 32 + y]);
    }
}

// ---------------------------------------------------------------------- launch
extern "C" void kernel_launch(void* const* d_in, const int* in_sizes, int n_in,
                              void* d_out, int out_size) {
    const float* q     = (const float*)d_in[0];
    const float* f_emb = (const float*)d_in[1];
    const float* alog  = (const float*)d_in[2];
    const float* W1q   = (const float*)d_in[3];
    const float* W1f   = (const float*)d_in[4];
    const float* b1    = (const float*)d_in[5];
    const float* W2    = (const float*)d_in[6];
    const float* b2    = (const float*)d_in[7];
    const float* Wout  = (const float*)d_in[8];
    const float* bout  = (const float*)d_in[9];
    float* out = (float*)d_out;

    // split(jax.random.key(1), 2), partitionable: subkey_i = tf(key, (0, i))
    uint32_t kc0, kc1, ke0, ke1;
    tf2x32(0u, 1u, 0u, 0u, kc0, kc1);
    tf2x32(0u, 1u, 0u, 1u, ke0, ke1);

    pp_fused_kernel<<<(B_ * QL_) / R_, 1024>>>(q, f_emb, alog, W1q, W1f, b1,
                                               W2, b2, Wout, bout, out,
                                               kc0, kc1, ke0, ke1);
}

// round 6
// speedup vs baseline: 1.4579x; 1.4579x over previous
#include <cuda_runtime.h>
#include <stdint.h>

// ProbabilisticPrediction fused kernel, R6 = R4 structure (8 rows/block,
// 1024 threads, 8-way d-split) + MUFU lg2 Gumbel + pipelined weight loads
// + merged idx-reduce/f-gather. Gumbel-argmax (JAX threefry partitionable)
// selects one mixture component per (b,q); MLP evaluated only there.

#define B_   4
#define QL_  256
#define CL_  512
#define DIM_ 128
#define YD_  16
#define R_   8

// ---------------------------------------------------------------- threefry2x32
__host__ __device__ inline void tf2x32(uint32_t k0, uint32_t k1,
                                       uint32_t c0, uint32_t c1,
                                       uint32_t& o0, uint32_t& o1) {
    uint32_t k2 = k0 ^ k1 ^ 0x1BD11BDAu;
    uint32_t x0 = c0 + k0, x1 = c1 + k1;
#define TFR(d) do { x0 += x1; x1 = (x1 << (d)) | (x1 >> (32 - (d))); x1 ^= x0; } while (0)
    TFR(13); TFR(15); TFR(26); TFR(6);   x0 += k1; x1 += k2 + 1u;
    TFR(17); TFR(29); TFR(16); TFR(24);  x0 += k2; x1 += k0 + 2u;
    TFR(13); TFR(15); TFR(26); TFR(6);   x0 += k0; x1 += k1 + 3u;
    TFR(17); TFR(29); TFR(16); TFR(24);  x0 += k1; x1 += k2 + 4u;
    TFR(13); TFR(15); TFR(26); TFR(6);   x0 += k2; x1 += k0 + 5u;
#undef TFR
    o0 = x0; o1 = x1;
}

__device__ inline uint32_t jax_bits(uint32_t k0, uint32_t k1, uint32_t j) {
    uint32_t o0, o1;
    tf2x32(k0, k1, 0u, j, o0, o1);   // partitionable: 64-bit iota (0, j)
    return o0 ^ o1;
}

__device__ inline float bits_to_unit(uint32_t b) {      // [0, 1)
    return __uint_as_float((b >> 9) | 0x3f800000u) - 1.0f;
}

// XLA ErfInv32 (Giles) -- matches jax.random.normal exactly.
__device__ inline float erfinv_xla(float x) {
    float w = -log1pf(-x * x);
    float p;
    if (w < 5.0f) {
        w -= 2.5f;
        p =            2.81022636e-08f;
        p = fmaf(p, w, 3.43273939e-07f);
        p = fmaf(p, w, -3.5233877e-06f);
        p = fmaf(p, w, -4.39150654e-06f);
        p = fmaf(p, w, 0.00021858087f);
        p = fmaf(p, w, -0.00125372503f);
        p = fmaf(p, w, -0.00417768164f);
        p = fmaf(p, w, 0.246640727f);
        p = fmaf(p, w, 1.50140941f);
    } else {
        w = sqrtf(w) - 3.0f;
        p =            -0.000200214257f;
        p = fmaf(p, w, 0.000100950558f);
        p = fmaf(p, w, 0.00134934322f);
        p = fmaf(p, w, -0.00367342844f);
        p = fmaf(p, w, 0.00573950773f);
        p = fmaf(p, w, -0.0076224613f);
        p = fmaf(p, w, 0.00943887047f);
        p = fmaf(p, w, 1.00167406f);
        p = fmaf(p, w, 2.83297682f);
    }
    return p * x;
}

// ---------------------------------------------------------------------- kernel
__global__ __launch_bounds__(1024, 1)
void pp_fused_kernel(const float* __restrict__ q,
                     const float* __restrict__ f_embed,
                     const float* __restrict__ att_logits,
                     const float* __restrict__ W1q,
                     const float* __restrict__ W1f,
                     const float* __restrict__ b1,
                     const float* __restrict__ W2,
                     const float* __restrict__ b2,
                     const float* __restrict__ Wout,
                     const float* __restrict__ bout,
                     float* __restrict__ out,
                     uint32_t kc0, uint32_t kc1,
                     uint32_t ke0, uint32_t ke1)
{
    const int t   = threadIdx.x;         // 0..1023
    const int w   = t >> 5;              // warp 0..31
    const int ln  = t & 31;
    const int bq0 = blockIdx.x * R_;
    const int b   = bq0 >> 8;            // all R_ rows share b (8 | 256)

    __shared__ float sQ[R_ * DIM_];      // q rows; later h2
    __shared__ float sF[R_ * DIM_];      // selected f rows
    __shared__ float sH[R_ * DIM_];      // h1
    __shared__ float sPar[8 * R_ * DIM_];// 8-way partials (32KB); reused L3
    __shared__ float sO[R_ * 2 * YD_];
    __shared__ float sVal[32];
    __shared__ int   sIdxW[32];

    // Prefetch q rows (hidden under phase-1 ALU).
    if (t < 256)
        ((float4*)sQ)[t] = ((const float4*)(q + (size_t)bq0 * DIM_))[t];

    // -------- Phase 1: Gumbel-argmax; row r = w>>2, sub-range sub = w&3 -----
    {
        const int r = w >> 2, sub = w & 3;
        const int bq = bq0 + r;
        const float* lrow = att_logits + (size_t)bq * CL_;
        const float TINY = 1.17549435e-38f;
        float best = -__int_as_float(0x7f800000);
        int bi = 0;
#pragma unroll
        for (int i = 0; i < 4; ++i) {
            int c = sub * 128 + i * 32 + ln;
            uint32_t j = (uint32_t)bq * (uint32_t)CL_ + (uint32_t)c;
            float u = bits_to_unit(jax_bits(kc0, kc1, j));
            u = fmaxf(TINY, u * (1.0f - TINY) + TINY);
            // g = -log(-log(u)) = -ln2*log2(-log2(u)*ln2) computed as
            //     -ln2*log2(-log2(u)) - ln(ln2)
            float lg1; asm("lg2.approx.f32 %0, %1;" : "=f"(lg1) : "f"(u));
            float L = -lg1;
            float lg2v; asm("lg2.approx.f32 %0, %1;" : "=f"(lg2v) : "f"(L));
            float g = fmaf(-0.693147180559945f, lg2v, 0.366512920581664f);
            float v = g + lrow[c];
            if (v > best || (v == best && c < bi)) { best = v; bi = c; }
        }
#pragma unroll
        for (int off = 16; off; off >>= 1) {
            float v2 = __shfl_xor_sync(0xffffffffu, best, off);
            int   i2 = __shfl_xor_sync(0xffffffffu, bi,   off);
            if (v2 > best || (v2 == best && i2 < bi)) { best = v2; bi = i2; }
        }
        if (ln == 0) { sVal[w] = best; sIdxW[w] = bi; }
    }
    __syncthreads();
    if (t < 256) {   // warp r (=w<8): finalize row-r argmax + gather f row
        const int r = w;
        float bv = sVal[r * 4]; int bj = sIdxW[r * 4];
#pragma unroll
        for (int k = 1; k < 4; ++k) {
            float v2 = sVal[r * 4 + k]; int i2 = sIdxW[r * 4 + k];
            if (v2 > bv || (v2 == bv && i2 < bj)) { bv = v2; bj = i2; }
        }
        // bj is lane-uniform within warp r
        ((float4*)(sF + r * DIM_))[ln] =
            ((const float4*)(f_embed + ((size_t)b * CL_ + bj) * DIM_))[ln];
    }
    __syncthreads();

    const int c   = t & 127;             // output column
    const int oct = t >> 7;              // d-octant 0..7 (16 d's each)

    // -------- Layer 1: h = relu(q@W1q + f@W1f + b1), pipelined loads --------
    {
        float acc[R_];
#pragma unroll
        for (int r = 0; r < R_; ++r) acc[r] = 0.f;
        const float* wq = W1q + c;
        const float* wf = W1f + c;
        float cq0, cq1, cq2, cq3, cf0, cf1, cf2, cf3;
        {
            const int d = oct * 16;
            cq0 = wq[(d + 0) * DIM_]; cq1 = wq[(d + 1) * DIM_];
            cq2 = wq[(d + 2) * DIM_]; cq3 = wq[(d + 3) * DIM_];
            cf0 = wf[(d + 0) * DIM_]; cf1 = wf[(d + 1) * DIM_];
            cf2 = wf[(d + 2) * DIM_]; cf3 = wf[(d + 3) * DIM_];
        }
#pragma unroll
        for (int i = 0; i < 4; ++i) {
            float nq0, nq1, nq2, nq3, nf0, nf1, nf2, nf3;
            if (i < 3) {                // prefetch next iteration's weights
                const int dn = oct * 16 + (i + 1) * 4;
                nq0 = wq[(dn + 0) * DIM_]; nq1 = wq[(dn + 1) * DIM_];
                nq2 = wq[(dn + 2) * DIM_]; nq3 = wq[(dn + 3) * DIM_];
                nf0 = wf[(dn + 0) * DIM_]; nf1 = wf[(dn + 1) * DIM_];
                nf2 = wf[(dn + 2) * DIM_]; nf3 = wf[(dn + 3) * DIM_];
            }
            const int d = oct * 16 + i * 4;
#pragma unroll
            for (int r = 0; r < R_; ++r) {
                float4 qv = ((const float4*)sQ)[r * 32 + (d >> 2)];
                float4 fv = ((const float4*)sF)[r * 32 + (d >> 2)];
                acc[r] = fmaf(qv.x, cq0, acc[r]); acc[r] = fmaf(qv.y, cq1, acc[r]);
                acc[r] = fmaf(qv.z, cq2, acc[r]); acc[r] = fmaf(qv.w, cq3, acc[r]);
                acc[r] = fmaf(fv.x, cf0, acc[r]); acc[r] = fmaf(fv.y, cf1, acc[r]);
                acc[r] = fmaf(fv.z, cf2, acc[r]); acc[r] = fmaf(fv.w, cf3, acc[r]);
            }
            if (i < 3) {
                cq0 = nq0; cq1 = nq1; cq2 = nq2; cq3 = nq3;
                cf0 = nf0; cf1 = nf1; cf2 = nf2; cf3 = nf3;
            }
        }
#pragma unroll
        for (int r = 0; r < R_; ++r) sPar[oct * 1024 + r * DIM_ + c] = acc[r];
    }
    __syncthreads();
    {
        float s = 0.f;
#pragma unroll
        for (int k = 0; k < 8; ++k) s += sPar[k * 1024 + t];
        sH[t] = fmaxf(s + b1[c], 0.f);
    }
    __syncthreads();

    // -------- Layer 2: h2 = relu(h@W2 + b2), pipelined loads ----------------
    {
        float acc[R_];
#pragma unroll
        for (int r = 0; r < R_; ++r) acc[r] = 0.f;
        const float* w2 = W2 + c;
        float c0, c1, c2, c3;
        {
            const int d = oct * 16;
            c0 = w2[(d + 0) * DIM_]; c1 = w2[(d + 1) * DIM_];
            c2 = w2[(d + 2) * DIM_]; c3 = w2[(d + 3) * DIM_];
        }
#pragma unroll
        for (int i = 0; i < 4; ++i) {
            float n0, n1, n2, n3;
            if (i < 3) {
                const int dn = oct * 16 + (i + 1) * 4;
                n0 = w2[(dn + 0) * DIM_]; n1 = w2[(dn + 1) * DIM_];
                n2 = w2[(dn + 2) * DIM_]; n3 = w2[(dn + 3) * DIM_];
            }
            const int d = oct * 16 + i * 4;
#pragma unroll
            for (int r = 0; r < R_; ++r) {
                float4 hv = ((const float4*)sH)[r * 32 + (d >> 2)];
                acc[r] = fmaf(hv.x, c0, acc[r]); acc[r] = fmaf(hv.y, c1, acc[r]);
                acc[r] = fmaf(hv.z, c2, acc[r]); acc[r] = fmaf(hv.w, c3, acc[r]);
            }
            if (i < 3) { c0 = n0; c1 = n1; c2 = n2; c3 = n3; }
        }
#pragma unroll
        for (int r = 0; r < R_; ++r) sPar[oct * 1024 + r * DIM_ + c] = acc[r];
    }
    __syncthreads();
    {
        float s = 0.f;
#pragma unroll
        for (int k = 0; k < 8; ++k) s += sPar[k * 1024 + t];
        sQ[t] = fmaxf(s + b2[c], 0.f);   // sQ := h2
    }
    __syncthreads();

    // -------- Layer 3: out = h2@Wout + bout  (4-way d-split) ----------------
    {
        const int p  = t >> 8;           // 0..3, d in [p*32, p*32+32)
        const int rr = (t >> 5) & 7;
        const int o  = ln;
        float a0 = 0.f, a1 = 0.f;
#pragma unroll
        for (int d4 = 0; d4 < 8; ++d4) {
            const int d = p * 32 + d4 * 4;
            float4 hv = ((const float4*)sQ)[rr * 32 + (d >> 2)];
            a0 = fmaf(hv.x, Wout[(d + 0) * 32 + o], a0);
            a1 = fmaf(hv.y, Wout[(d + 1) * 32 + o], a1);
            a0 = fmaf(hv.z, Wout[(d + 2) * 32 + o], a0);
            a1 = fmaf(hv.w, Wout[(d + 3) * 32 + o], a1);
        }
        sPar[p * 256 + rr * 32 + o] = a0 + a1;
    }
    __syncthreads();
    if (t < 256) {
        sO[t] = sPar[t] + sPar[256 + t] + sPar[512 + t] + sPar[768 + t]
              + bout[t & 31];
    }
    __syncthreads();

    // -------- Sample: y = mu + softplus(max(-15,s)) * eps -------------------
    if (t < R_ * YD_) {                  // 128 threads
        const int rr = t >> 4, y = t & 15;
        uint32_t m = (uint32_t)(bq0 + rr) * (uint32_t)YD_ + (uint32_t)y;
        float u = bits_to_unit(jax_bits(ke0, ke1, m));
        const float lo = -0.99999994f;
        float x = fmaxf(lo, u * (1.0f - lo) + lo);
        float eps = 1.41421356237f * erfinv_xla(x);
        float s = fmaxf(-15.0f, sO[rr * 32 + YD_ + y]);
        float sigma = fmaxf(s, 0.0f) + log1pf(expf(-fabsf(s)));
        out[(size_t)bq0 * YD_ + t] = fmaf(sigma, eps, sO[rr * 32 + y]);
    }
}

// ---------------------------------------------------------------------- launch
extern "C" void kernel_launch(void* const* d_in, const int* in_sizes, int n_in,
                              void* d_out, int out_size) {
    const float* q     = (const float*)d_in[0];
    const float* f_emb = (const float*)d_in[1];
    const float* alog  = (const float*)d_in[2];
    const float* W1q   = (const float*)d_in[3];
    const float* W1f   = (const float*)d_in[4];
    const float* b1    = (const float*)d_in[5];
    const float* W2    = (const float*)d_in[6];
    const float* b2    = (const float*)d_in[7];
    const float* Wout  = (const float*)d_in[8];
    const float* bout  = (const float*)d_in[9];
    float* out = (float*)d_out;

    // split(jax.random.key(1), 2), partitionable: subkey_i = tf(key, (0, i))
    uint32_t kc0, kc1, ke0, ke1;
    tf2x32(0u, 1u, 0u, 0u, kc0, kc1);
    tf2x32(0u, 1u, 0u, 1u, ke0, ke1);

    pp_fused_kernel<<<(B_ * QL_) / R_, 1024>>>(q, f_emb, alog, W1q, W1f, b1,
                                               W2, b2, Wout, bout, out,
                                               kc0, kc1, ke0, ke1);
}